// round 3
// baseline (speedup 1.0000x reference)
#include <cuda_runtime.h>
#include <stdint.h>

// adjacency_full[i, neighbor_indices[i, j]] = adjacency_values[i, j]
// N = 8192, K = 64. Output: N*N fp32 (256 MB).
//
// One CTA per row. Instead of materializing the 32KB row in shared memory
// (96KB smem traffic/row, occ-limiting), keep only:
//   - a 1KB presence bitmap (8192 bits)
//   - the 64 (col, val) pairs (512B)
// Streaming phase: each thread stores zero float4s straight from registers;
// the bitmap nibble tells it the rare chunks (~64/2048) that need a value
// lookup in the 64-entry list.

#define N_PATCHES 8192
#define K_NEIGH   64
#define THREADS   256
#define CHUNKS    (N_PATCHES / 4)        // 2048 float4 per row
#define PER_THR   (CHUNKS / THREADS)     // 8 chunks per thread
#define BM_WORDS  (N_PATCHES / 32)       // 256 uint32

__global__ __launch_bounds__(THREADS)
void fused_bitmap_kernel(const float* __restrict__ vals,
                         const int*   __restrict__ idx,
                         float* __restrict__ out)
{
    __shared__ unsigned bitmap[BM_WORDS];   // 1 KB
    __shared__ int      scol[K_NEIGH];      // 256 B
    __shared__ float    sval[K_NEIGH];      // 256 B

    const int r   = blockIdx.x;
    const int tid = threadIdx.x;

    // 1) Zero bitmap (exactly one word per thread).
    bitmap[tid] = 0u;
    __syncthreads();

    // 2) Load this row's 64 (col, val) pairs; set presence bits.
    if (tid < K_NEIGH) {
        int t = r * K_NEIGH + tid;
        int c = idx[t];                  // coalesced
        scol[tid] = c;
        sval[tid] = vals[t];             // coalesced
        atomicOr(&bitmap[c >> 5], 1u << (c & 31));
    }
    __syncthreads();

    // 3) Stream the row: mostly zero float4 stores straight from registers.
    float4* out4 = reinterpret_cast<float4*>(out + (size_t)r * N_PATCHES);
    const float4 z4 = make_float4(0.f, 0.f, 0.f, 0.f);

    #pragma unroll
    for (int j = 0; j < PER_THR; j++) {
        int c4 = tid + j * THREADS;                       // chunk index (4 cols)
        unsigned w   = bitmap[c4 >> 3];                   // broadcast-ish LDS
        unsigned nib = (w >> ((c4 & 7) * 4)) & 0xFu;
        if (nib == 0u) {
            __stcs(&out4[c4], z4);                        // common path
        } else {
            float4 v = z4;
            #pragma unroll 4
            for (int e = 0; e < K_NEIGH; e++) {           // rare: ~64 hits/row
                int c = scol[e];
                if ((c >> 2) == c4)
                    reinterpret_cast<float*>(&v)[c & 3] = sval[e];
            }
            __stcs(&out4[c4], v);
        }
    }
}

extern "C" void kernel_launch(void* const* d_in, const int* in_sizes, int n_in,
                              void* d_out, int out_size)
{
    const float* vals = (const float*)d_in[0];   // [N, K] float32
    const int*   idx  = (const int*)  d_in[1];   // [N, K] int32
    float* out = (float*)d_out;                  // [N, N] float32

    fused_bitmap_kernel<<<N_PATCHES, THREADS, 0, 0>>>(vals, idx, out);
}

// round 4
// speedup vs baseline: 3.5751x; 3.5751x over previous
#include <cuda_runtime.h>
#include <stdint.h>

// adjacency_full[i, neighbor_indices[i, j]] = adjacency_values[i, j]
// N = 8192, K = 64. Output: N*N fp32 (256 MB).
//
// One CTA per row, no shared memory:
//   phase 1: stream 8192 zeros (2048 x STG.128) from registers — pure fill.
//   barrier: intra-CTA happens-before (zero-writes ordered before value-writes).
//   phase 2: threads 0..63 scatter the row's 64 values (4B stores that hit
//            the just-written, still-in-L2 lines — no extra DRAM traffic).

#define N_PATCHES 8192
#define K_NEIGH   64
#define THREADS   256
#define CHUNKS    (N_PATCHES / 4)        // 2048 float4 per row
#define PER_THR   (CHUNKS / THREADS)     // 8 chunks per thread

__global__ __launch_bounds__(THREADS)
void fused_zero_scatter_kernel(const float* __restrict__ vals,
                               const int*   __restrict__ idx,
                               float* __restrict__ out)
{
    const int r   = blockIdx.x;
    const int tid = threadIdx.x;

    float4* out4 = reinterpret_cast<float4*>(out + (size_t)r * N_PATCHES);
    const float4 z4 = make_float4(0.f, 0.f, 0.f, 0.f);

    // Phase 1: fully-coalesced zero fill, 8 independent STG.128 per thread.
    #pragma unroll
    for (int j = 0; j < PER_THR; j++)
        out4[tid + j * THREADS] = z4;

    // Order: all zero-stores of this CTA happen-before the value stores.
    __syncthreads();

    // Phase 2: scatter the 64 values (lines still hot in L2).
    if (tid < K_NEIGH) {
        int t = r * K_NEIGH + tid;
        int c = idx[t];                          // coalesced read
        out[(size_t)r * N_PATCHES + c] = vals[t]; // in-L2 4B store
    }
}

extern "C" void kernel_launch(void* const* d_in, const int* in_sizes, int n_in,
                              void* d_out, int out_size)
{
    const float* vals = (const float*)d_in[0];   // [N, K] float32
    const int*   idx  = (const int*)  d_in[1];   // [N, K] int32
    float* out = (float*)d_out;                  // [N, N] float32

    fused_zero_scatter_kernel<<<N_PATCHES, THREADS, 0, 0>>>(vals, idx, out);
}